// round 11
// baseline (speedup 1.0000x reference)
#include <cuda_runtime.h>
#include <cuda_fp16.h>
#include <cstdint>

// Problem constants
#define CB   8
#define HW   4096          // 64*64
#define CIN  512

// Device scratch (fp16: same 11-bit significand as tf32 -> bit-equivalent)
static __device__ __half g_rpn1h[(size_t)CB * 384 * HW]; // conv3 out (24MB)
static __device__ __half g_feath[(size_t)CB * 128 * HW]; // convf_rpn (8MB)
static __device__ __half g_wah[512 * 512];               // [w_f; w_2]
static __device__ __half g_wth[9 * 384 * 128];           // w_c1 tap-major
static __device__ __half g_whh[64 * 384];                // [w_cls; w_box; 0]

// ---------------------------------------------------------------------------
// helpers
// ---------------------------------------------------------------------------
__device__ __forceinline__ unsigned f2tf(float x) {
    unsigned r;
    asm("cvt.rna.tf32.f32 %0, %1;" : "=r"(r) : "f"(x));
    return r;
}
__device__ __forceinline__ unsigned h2u(__half h) {
    return __float_as_uint(__half2float(h));
}

__device__ __forceinline__ void mma8(float d[4], const unsigned a[4], const unsigned b[2]) {
    asm volatile(
        "mma.sync.aligned.m16n8k8.row.col.f32.tf32.tf32.f32 "
        "{%0,%1,%2,%3}, {%4,%5,%6,%7}, {%8,%9}, {%0,%1,%2,%3};\n"
        : "+f"(d[0]), "+f"(d[1]), "+f"(d[2]), "+f"(d[3])
        : "r"(a[0]), "r"(a[1]), "r"(a[2]), "r"(a[3]), "r"(b[0]), "r"(b[1]));
}

__device__ __forceinline__ unsigned sptr(const void* p) {
    return (unsigned)__cvta_generic_to_shared(p);
}
__device__ __forceinline__ void cp16(unsigned d, const void* s, bool ok) {
    asm volatile("cp.async.cg.shared.global [%0], [%1], 16, %2;\n"
                 :: "r"(d), "l"(s), "r"(ok ? 16 : 0));
}
__device__ __forceinline__ void cpcommit() { asm volatile("cp.async.commit_group;\n"); }
__device__ __forceinline__ void cpwait1()  { asm volatile("cp.async.wait_group 1;\n"); }

// ---------------------------------------------------------------------------
// Prep: convert weights to fp16 (== tf32 rounding for 11-bit significand),
// transpose w_c1 to tap-major, pack head weights branchless.
// ---------------------------------------------------------------------------
#define PREP_N1 262144              // 512*512
#define PREP_N2 442368              // 9*384*128
#define PREP_N3 24576               // 64*384
#define PREP_TOT (PREP_N1 + PREP_N2 + PREP_N3)

__global__ void k_prep(const float* __restrict__ w_f, const float* __restrict__ w_2,
                       const float* __restrict__ w_c1,
                       const float* __restrict__ w_cls, const float* __restrict__ w_box)
{
    int i = blockIdx.x * 256 + threadIdx.x;
    if (i < PREP_N1) {
        int m = i >> 9;
        float v = (m < 128) ? w_f[i] : w_2[i - 65536];
        g_wah[i] = __float2half_rn(v);
        return;
    }
    i -= PREP_N1;
    if (i < PREP_N2) {
        int tap = i / 49152, rem = i % 49152;
        int m = rem >> 7, c = rem & 127;
        g_wth[i] = __float2half_rn(w_c1[(size_t)m * 1152 + c * 9 + tap]);
        return;
    }
    i -= PREP_N2;
    if (i < PREP_N3) {
        int r = i / 384, k = i - r * 384;
        float v;
        if (r < 18)      v = w_cls[i];
        else if (r < 54) v = w_box[(r - 18) * 384 + k];
        else             v = 0.f;
        g_whh[i] = __float2half_rn(v);
    }
}

// ---------------------------------------------------------------------------
// Kernel 1: fused 1x1 conv 512 -> 512, ReLU -> d_out feat region.
// 4 warps of 64x64 (128 thr). 6-stage ring, K=16/stage, TWO stages per
// barrier (2 commits/iter; wait1 => stages <= 2u+2 complete at iter top).
// A fp16 [128][24] per stage; B f32 [16][136]. Fragment register pipeline.
// mt==0 also writes fp16 channels 0..127 to g_feath.
// ---------------------------------------------------------------------------
#define C1_ST_B 14848               // 6144 (A fp16) + 8704 (B f32)
#define C1_SMEM (6 * C1_ST_B)       // 89088 bytes

__global__ __launch_bounds__(128, 2)
void k_conv1(const float* __restrict__ base_feat,
             const float* __restrict__ b_f, const float* __restrict__ b_2,
             float* __restrict__ out)
{
    extern __shared__ char ds[];
    const int n  = blockIdx.z;
    const int mt = blockIdx.y;
    const int n0 = blockIdx.x * 128;
    const int mtb = mt * 128;
    const float* bi = (mt == 0) ? b_f : (b_2 + (mt - 1) * 128);
    const float* Bp = base_feat + (size_t)n * CIN * HW + n0;

    const int tid  = threadIdx.x;
    const int warp = tid >> 5, lane = tid & 31;
    const int wm = (warp >> 1) * 64, wn = (warp & 1) * 64;
    const int g  = lane >> 2, t4 = lane & 3;

    auto loadT = [&](int s) {
        if (s < 32) {
            char* As = ds + (s % 6) * C1_ST_B;
            char* Bs = As + 6144;
            const int k0 = s * 16;
            #pragma unroll
            for (int j = 0; j < 2; j++) {
                int e = tid + j * 128;            // 0..255
                int row = e >> 1, sub = e & 1;
                cp16(sptr(As + row * 48 + sub * 16),
                     g_wah + (size_t)(mtb + row) * 512 + k0 + sub * 8, true);
            }
            #pragma unroll
            for (int j = 0; j < 4; j++) {
                int e = tid + j * 128;            // 0..511
                cp16(sptr(Bs + (e >> 5) * 544 + (e & 31) * 16),
                     Bp + (size_t)(k0 + (e >> 5)) * HW + (e & 31) * 4, true);
            }
        }
        cpcommit();
    };

    auto ldfrag = [&](int s, int kk, unsigned (&a)[4][4], unsigned (&b)[8][2]) {
        const __half* As = (const __half*)(ds + (s % 6) * C1_ST_B);
        const float*  Bs = (const float*)(ds + (s % 6) * C1_ST_B + 6144);
        #pragma unroll
        for (int mf = 0; mf < 4; mf++) {
            int r = wm + mf * 16;
            a[mf][0] = h2u(As[(r + g) * 24 + kk + t4]);
            a[mf][1] = h2u(As[(r + g + 8) * 24 + kk + t4]);
            a[mf][2] = h2u(As[(r + g) * 24 + kk + t4 + 4]);
            a[mf][3] = h2u(As[(r + g + 8) * 24 + kk + t4 + 4]);
        }
        #pragma unroll
        for (int nf = 0; nf < 8; nf++) {
            int c = wn + nf * 8 + g;
            b[nf][0] = f2tf(Bs[(kk + t4) * 136 + c]);
            b[nf][1] = f2tf(Bs[(kk + t4 + 4) * 136 + c]);
        }
    };

    float acc[4][8][4] = {};
    unsigned aA[4][4], bA[8][2], aB[4][4], bB[8][2];

    loadT(0); loadT(1); loadT(2); loadT(3);
    cpwait1();                                  // stages 0..2 complete
    __syncthreads();
    ldfrag(0, 0, aA, bA);

    for (int u = 0; u < 16; u++) {
        // invariant: stages <= 2u+2 complete & visible
        loadT(2 * u + 4); loadT(2 * u + 5);
        const int s0 = 2 * u, s1 = 2 * u + 1;

        ldfrag(s0, 8, aB, bB);
        #pragma unroll
        for (int mf = 0; mf < 4; mf++)
            #pragma unroll
            for (int nf = 0; nf < 8; nf++) mma8(acc[mf][nf], aA[mf], bA[nf]);
        ldfrag(s1, 0, aA, bA);
        #pragma unroll
        for (int mf = 0; mf < 4; mf++)
            #pragma unroll
            for (int nf = 0; nf < 8; nf++) mma8(acc[mf][nf], aB[mf], bB[nf]);
        ldfrag(s1, 8, aB, bB);
        #pragma unroll
        for (int mf = 0; mf < 4; mf++)
            #pragma unroll
            for (int nf = 0; nf < 8; nf++) mma8(acc[mf][nf], aA[mf], bA[nf]);
        if (u + 1 < 16) ldfrag(s0 + 2, 0, aA, bA);
        #pragma unroll
        for (int mf = 0; mf < 4; mf++)
            #pragma unroll
            for (int nf = 0; nf < 8; nf++) mma8(acc[mf][nf], aB[mf], bB[nf]);

        if (u + 1 < 16) { cpwait1(); __syncthreads(); }
    }

    float*  outb = out + (size_t)n * CIN * HW + (size_t)mt * 128 * HW;
    __half* fh   = g_feath + (size_t)n * 128 * HW;
    #pragma unroll
    for (int mf = 0; mf < 4; mf++) {
        int r0 = wm + mf * 16 + g;
        float bv0 = bi[r0], bv1 = bi[r0 + 8];
        #pragma unroll
        for (int nf = 0; nf < 8; nf++) {
            int c = n0 + wn + nf * 8 + t4 * 2;
            float2 v0, v1;
            v0.x = fmaxf(acc[mf][nf][0] + bv0, 0.f);
            v0.y = fmaxf(acc[mf][nf][1] + bv0, 0.f);
            v1.x = fmaxf(acc[mf][nf][2] + bv1, 0.f);
            v1.y = fmaxf(acc[mf][nf][3] + bv1, 0.f);
            *(float2*)(outb + (size_t)r0 * HW + c)       = v0;
            *(float2*)(outb + (size_t)(r0 + 8) * HW + c) = v1;
            if (mt == 0) {
                *(__half2*)(fh + (size_t)r0 * HW + c)       = __floats2half2_rn(v0.x, v0.y);
                *(__half2*)(fh + (size_t)(r0 + 8) * HW + c) = __floats2half2_rn(v1.x, v1.y);
            }
        }
    }
}

// ---------------------------------------------------------------------------
// Kernel 2: 3x3 conv 128 -> 384 pad=1, ReLU -> g_rpn1h (fp16).
// 72 (kc,tap) stages, 2 per barrier, 6-stage fp16 A-ring. H in fp16:
// slice = [8 zero pad halves][4 rows of 72 halves], cols 64..71 zeroed;
// 2 buffers at kc cadence, bundled into stage-9kc commit groups.
// ---------------------------------------------------------------------------
#define H_ROWH   72
#define H_PADH   8
#define H_SLICEH 296                // halves (592B)
#define H_BUFH   (16 * H_SLICEH)    // 4736 halves (9472B)
#define C3_A_B   6144               // bytes per A stage (128*24 halves)
#define C3_SMEM  (6 * C3_A_B + 2 * H_BUFH * 2)   // 36864 + 18944 = 55808

__global__ __launch_bounds__(128, 2)
void k_conv3(const float* __restrict__ b_c1)
{
    extern __shared__ char ds[];
    __half* Hbh = (__half*)(ds + 6 * C3_A_B);

    const int n  = blockIdx.z;
    const int m0 = blockIdx.y * 128;
    const int n0 = blockIdx.x * 128;
    const int y0 = blockIdx.x * 2;

    const int tid  = threadIdx.x;
    const int warp = tid >> 5, lane = tid & 31;
    const int wm = (warp >> 1) * 64, wn = (warp & 1) * 64;
    const int g  = lane >> 2, t4 = lane & 3;

    // zero pads: per (buf,k): front 8 halves + halo cols 64..71 of 4 rows
    for (int i = tid; i < 1280; i += 128) {
        int buf = i / 640, r2 = i % 640;
        int k = r2 / 40, e = r2 % 40;
        int off = (e < 8) ? e
                          : H_PADH + ((e - 8) >> 3) * H_ROWH + 64 + ((e - 8) & 7);
        Hbh[buf * H_BUFH + k * H_SLICEH + off] = __float2half(0.f);
    }

    auto loadH = [&](int kc, int buf) {
        #pragma unroll
        for (int j = 0; j < 4; j++) {
            int e = tid + j * 128;                 // 0..511
            int k = e >> 5, rem = e & 31, r = rem >> 3, xu = rem & 7;
            int gy = y0 - 1 + r;
            cp16(sptr(Hbh + buf * H_BUFH + k * H_SLICEH + H_PADH + r * H_ROWH + xu * 8),
                 g_feath + (size_t)n * 128 * HW + (size_t)(kc * 16 + k) * HW + gy * 64 + xu * 8,
                 (unsigned)gy < 64u);
        }
    };
    auto loadT = [&](int s) {
        if (s < 72) {
            int kc = s / 9, tap = s - kc * 9;
            char* As = ds + (s % 6) * C3_A_B;
            #pragma unroll
            for (int j = 0; j < 2; j++) {
                int e = tid + j * 128;             // 0..255
                int row = e >> 1, sub = e & 1;
                cp16(sptr(As + row * 48 + sub * 16),
                     g_wth + ((size_t)tap * 384 + m0 + row) * 128 + kc * 16 + sub * 8, true);
            }
            if (tap == 0 && kc < 8) loadH(kc, kc & 1);
        }
        cpcommit();
    };

    int ib[8];
    #pragma unroll
    for (int nf = 0; nf < 8; nf++) {
        int px = wn + nf * 8 + g;
        ib[nf] = H_PADH + (1 + (px >> 6)) * H_ROWH + (px & 63);
    }

    auto ldfrag = [&](int s, int kk, unsigned (&a)[4][4], unsigned (&b)[8][2]) {
        int kc = s / 9, tap = s - kc * 9;
        int hoff = (tap / 3 - 1) * H_ROWH + (tap % 3 - 1);
        const __half* As = (const __half*)(ds + (s % 6) * C3_A_B);
        const __half* Hc = Hbh + (kc & 1) * H_BUFH;
        #pragma unroll
        for (int mf = 0; mf < 4; mf++) {
            int r = wm + mf * 16;
            a[mf][0] = h2u(As[(r + g) * 24 + kk + t4]);
            a[mf][1] = h2u(As[(r + g + 8) * 24 + kk + t4]);
            a[mf][2] = h2u(As[(r + g) * 24 + kk + t4 + 4]);
            a[mf][3] = h2u(As[(r + g + 8) * 24 + kk + t4 + 4]);
        }
        #pragma unroll
        for (int nf = 0; nf < 8; nf++) {
            b[nf][0] = h2u(Hc[(kk + t4) * H_SLICEH + ib[nf] + hoff]);
            b[nf][1] = h2u(Hc[(kk + t4 + 4) * H_SLICEH + ib[nf] + hoff]);
        }
    };

    float acc[4][8][4] = {};
    unsigned aA[4][4], bA[8][2], aB[4][4], bB[8][2];

    loadT(0); loadT(1); loadT(2); loadT(3);     // stage0 commit includes H(0)
    cpwait1();
    __syncthreads();                             // pads + stages 0..2 visible
    ldfrag(0, 0, aA, bA);

    for (int u = 0; u < 36; u++) {
        loadT(2 * u + 4); loadT(2 * u + 5);
        const int s0 = 2 * u, s1 = 2 * u + 1;

        ldfrag(s0, 8, aB, bB);
        #pragma unroll
        for (int mf = 0; mf < 4; mf++)
            #pragma unroll
            for (int nf = 0; nf < 8; nf++) mma8(acc[mf][nf], aA[mf], bA[nf]);
        ldfrag(s1, 0, aA, bA);
        #pragma unroll
        for (int mf = 0; mf < 4; mf++)
            #pragma unroll
            for (int nf = 0; nf < 8; nf++) mma8(acc[mf][nf], aB[mf], bB[nf]);
        ldfrag(s1, 8, aB, bB);
        #pragma unroll
        for (int mf = 0; mf < 4; mf++)
            #pragma unroll
            for (int nf = 0; nf < 8; nf++) mma8(acc[mf][nf], aA[mf], bA[nf]);
        if (u + 1 < 36) ldfrag(s0 + 2, 0, aA, bA);
        #pragma unroll
        for (int mf = 0; mf < 4; mf++)
            #pragma unroll
            for (int nf = 0; nf < 8; nf++) mma8(acc[mf][nf], aB[mf], bB[nf]);

        if (u + 1 < 36) { cpwait1(); __syncthreads(); }
    }

    __half* ob = g_rpn1h + (size_t)n * 384 * HW;
    #pragma unroll
    for (int mf = 0; mf < 4; mf++) {
        int r0 = m0 + wm + mf * 16 + g;
        float bv0 = b_c1[r0], bv1 = b_c1[r0 + 8];
        #pragma unroll
        for (int nf = 0; nf < 8; nf++) {
            int c = n0 + wn + nf * 8 + t4 * 2;
            float x0 = fmaxf(acc[mf][nf][0] + bv0, 0.f);
            float x1 = fmaxf(acc[mf][nf][1] + bv0, 0.f);
            float x2 = fmaxf(acc[mf][nf][2] + bv1, 0.f);
            float x3 = fmaxf(acc[mf][nf][3] + bv1, 0.f);
            *(__half2*)(ob + (size_t)r0 * HW + c)       = __floats2half2_rn(x0, x1);
            *(__half2*)(ob + (size_t)(r0 + 8) * HW + c) = __floats2half2_rn(x2, x3);
        }
    }
}

// ---------------------------------------------------------------------------
// Kernel 3: head. 4 warps of 32x64, 128 thr. B = g_rpn1h fp16 (24MB read).
// 24 K=16 stages, 2 per barrier, 6-stage ring, fragment pipeline.
// Bias + paired softmax (c, c+9) for cls, bias for box, two zero scalars.
// ---------------------------------------------------------------------------
#define HD_ST_B 7424                // 3072 (A fp16 64x24) + 4352 (B fp16 16x136)
#define HD_SMEM (6 * HD_ST_B)       // 44544 bytes

__global__ __launch_bounds__(128)
void k_head(const float* __restrict__ b_cls, const float* __restrict__ b_box,
            float* __restrict__ out)
{
    extern __shared__ char ds[];
    const int n  = blockIdx.z;
    const int n0 = blockIdx.x * 128;
    const __half* Bp = g_rpn1h + (size_t)n * 384 * HW + n0;

    const int tid  = threadIdx.x;
    const int warp = tid >> 5, lane = tid & 31;
    const int wm = (warp >> 1) * 32, wn = (warp & 1) * 64;
    const int g  = lane >> 2, t4 = lane & 3;

    auto loadT = [&](int s) {
        if (s < 24) {
            char* As = ds + (s % 6) * HD_ST_B;
            char* Bs = As + 3072;
            const int k0 = s * 16;
            {
                int row = tid >> 1, sub = tid & 1;  // 128 chunks
                cp16(sptr(As + row * 48 + sub * 16),
                     g_whh + (size_t)row * 384 + k0 + sub * 8, true);
            }
            #pragma unroll
            for (int j = 0; j < 2; j++) {
                int e = tid + j * 128;              // 0..255
                int row = e >> 4, xu = e & 15;
                cp16(sptr(Bs + row * 272 + xu * 16),
                     Bp + (size_t)(k0 + row) * HW + xu * 8, true);
            }
        }
        cpcommit();
    };

    auto ldfrag = [&](int s, int kk, unsigned (&a)[2][4], unsigned (&b)[8][2]) {
        const __half* As = (const __half*)(ds + (s % 6) * HD_ST_B);
        const __half* Bs = (const __half*)(ds + (s % 6) * HD_ST_B + 3072);
        #pragma unroll
        for (int mf = 0; mf < 2; mf++) {
            int r = wm + mf * 16;
            a[mf][0] = h2u(As[(r + g) * 24 + kk + t4]);
            a[mf][1] = h2u(As[(r + g + 8) * 24 + kk + t4]);
            a[mf][2] = h2u(As[(r + g) * 24 + kk + t4 + 4]);
            a[mf][3] = h2u(As[(r + g + 8) * 24 + kk + t4 + 4]);
        }
        #pragma unroll
        for (int nf = 0; nf < 8; nf++) {
            int c = wn + nf * 8 + g;
            b[nf][0] = h2u(Bs[(kk + t4) * 136 + c]);
            b[nf][1] = h2u(Bs[(kk + t4 + 4) * 136 + c]);
        }
    };

    float acc[2][8][4] = {};
    unsigned aA[2][4], bA[8][2], aB[2][4], bB[8][2];

    loadT(0); loadT(1); loadT(2); loadT(3);
    cpwait1();
    __syncthreads();
    ldfrag(0, 0, aA, bA);

    for (int u = 0; u < 12; u++) {
        loadT(2 * u + 4); loadT(2 * u + 5);
        const int s0 = 2 * u, s1 = 2 * u + 1;

        ldfrag(s0, 8, aB, bB);
        #pragma unroll
        for (int mf = 0; mf < 2; mf++)
            #pragma unroll
            for (int nf = 0; nf < 8; nf++) mma8(acc[mf][nf], aA[mf], bA[nf]);
        ldfrag(s1, 0, aA, bA);
        #pragma unroll
        for (int mf = 0; mf < 2; mf++)
            #pragma unroll
            for (int nf = 0; nf < 8; nf++) mma8(acc[mf][nf], aB[mf], bB[nf]);
        ldfrag(s1, 8, aB, bB);
        #pragma unroll
        for (int mf = 0; mf < 2; mf++)
            #pragma unroll
            for (int nf = 0; nf < 8; nf++) mma8(acc[mf][nf], aA[mf], bA[nf]);
        if (u + 1 < 12) ldfrag(s0 + 2, 0, aA, bA);
        #pragma unroll
        for (int mf = 0; mf < 2; mf++)
            #pragma unroll
            for (int nf = 0; nf < 8; nf++) mma8(acc[mf][nf], aB[mf], bB[nf]);

        if (u + 1 < 12) { cpwait1(); __syncthreads(); }
    }

    __syncthreads();                       // all warps done reading ring
    float (*Cs)[132] = (float(*)[132])ds;  // overlay (33792B < 44544B)
    #pragma unroll
    for (int mf = 0; mf < 2; mf++) {
        int r0 = wm + mf * 16 + g;
        #pragma unroll
        for (int nf = 0; nf < 8; nf++) {
            int c = wn + nf * 8 + t4 * 2;
            Cs[r0][c]         = acc[mf][nf][0];
            Cs[r0][c + 1]     = acc[mf][nf][1];
            Cs[r0 + 8][c]     = acc[mf][nf][2];
            Cs[r0 + 8][c + 1] = acc[mf][nf][3];
        }
    }
    __syncthreads();

    const size_t F1 = (size_t)CB * CIN * HW;
    const size_t F2 = F1 + (size_t)CB * 18 * HW;
    const size_t F3 = F2 + (size_t)CB * 36 * HW;

    for (int it = tid; it < 9 * 128; it += 128) {
        int c = it >> 7, j = it & 127;
        float s0 = Cs[c][j]     + b_cls[c];
        float s1 = Cs[c + 9][j] + b_cls[c + 9];
        float m  = fmaxf(s0, s1);
        float e0 = expf(s0 - m), e1 = expf(s1 - m);
        float inv = 1.f / (e0 + e1);
        out[F1 + (size_t)n * 18 * HW + (size_t)c * HW + n0 + j]       = e0 * inv;
        out[F1 + (size_t)n * 18 * HW + (size_t)(c + 9) * HW + n0 + j] = e1 * inv;
    }
    for (int it = tid; it < 36 * 128; it += 128) {
        int c = it >> 7, j = it & 127;
        out[F2 + (size_t)n * 36 * HW + (size_t)c * HW + n0 + j] = Cs[18 + c][j] + b_box[c];
    }
    if (n == 0 && blockIdx.x == 0 && tid == 0) {
        out[F3]     = 0.f;
        out[F3 + 1] = 0.f;
    }
}

// ---------------------------------------------------------------------------
extern "C" void kernel_launch(void* const* d_in, const int* in_sizes, int n_in,
                              void* d_out, int out_size)
{
    const float* base  = (const float*)d_in[0];
    const float* w_f   = (const float*)d_in[3];
    const float* b_f   = (const float*)d_in[4];
    const float* w_2   = (const float*)d_in[5];
    const float* b_2   = (const float*)d_in[6];
    const float* w_c1  = (const float*)d_in[7];
    const float* b_c1  = (const float*)d_in[8];
    const float* w_cls = (const float*)d_in[9];
    const float* b_cls = (const float*)d_in[10];
    const float* w_box = (const float*)d_in[11];
    const float* b_box = (const float*)d_in[12];
    float* out = (float*)d_out;

    static bool attr_set = false;
    if (!attr_set) {
        cudaFuncSetAttribute(k_conv1, cudaFuncAttributeMaxDynamicSharedMemorySize, C1_SMEM);
        cudaFuncSetAttribute(k_conv3, cudaFuncAttributeMaxDynamicSharedMemorySize, C3_SMEM);
        cudaFuncSetAttribute(k_head,  cudaFuncAttributeMaxDynamicSharedMemorySize, HD_SMEM);
        attr_set = true;
    }

    k_prep <<<(PREP_TOT + 255) / 256, 256>>>(w_f, w_2, w_c1, w_cls, w_box);
    k_conv1<<<dim3(32, 4, CB), 128, C1_SMEM>>>(base, b_f, b_2, out);
    k_conv3<<<dim3(32, 3, CB), 128, C3_SMEM>>>(b_c1);
    k_head <<<dim3(32, 1, CB), 128, HD_SMEM>>>(b_cls, b_box, out);
}

// round 12
// speedup vs baseline: 1.4727x; 1.4727x over previous
#include <cuda_runtime.h>
#include <cuda_fp16.h>
#include <cstdint>

// Problem constants
#define CB   8
#define HW   4096          // 64*64
#define CIN  512

// Device scratch (fp16: same 11-bit significand as tf32)
static __device__ __half g_bfh[(size_t)CB * 512 * HW];   // base_feat fp16 (32MB)
static __device__ __half g_rpn1h[(size_t)CB * 384 * HW]; // conv3 out (24MB)
static __device__ __half g_feath[(size_t)CB * 128 * HW]; // convf_rpn (8MB)
static __device__ __half g_wah[512 * 512];               // [w_f; w_2]
static __device__ __half g_wth[9 * 384 * 128];           // w_c1 tap-major
static __device__ __half g_whh[64 * 384];                // [w_cls; w_box; 0]

// ---------------------------------------------------------------------------
// helpers
// ---------------------------------------------------------------------------
__device__ __forceinline__ void mma16(float d[4], const unsigned a[4], const unsigned b[2]) {
    asm volatile(
        "mma.sync.aligned.m16n8k16.row.col.f32.f16.f16.f32 "
        "{%0,%1,%2,%3}, {%4,%5,%6,%7}, {%8,%9}, {%0,%1,%2,%3};\n"
        : "+f"(d[0]), "+f"(d[1]), "+f"(d[2]), "+f"(d[3])
        : "r"(a[0]), "r"(a[1]), "r"(a[2]), "r"(a[3]), "r"(b[0]), "r"(b[1]));
}

__device__ __forceinline__ unsigned sptr(const void* p) {
    return (unsigned)__cvta_generic_to_shared(p);
}
__device__ __forceinline__ void cp16(unsigned d, const void* s, bool ok) {
    asm volatile("cp.async.cg.shared.global [%0], [%1], 16, %2;\n"
                 :: "r"(d), "l"(s), "r"(ok ? 16 : 0));
}
__device__ __forceinline__ void cpcommit() { asm volatile("cp.async.commit_group;\n"); }
__device__ __forceinline__ void cpwait1()  { asm volatile("cp.async.wait_group 1;\n"); }

__device__ __forceinline__ void ldm4(unsigned addr, unsigned& r0, unsigned& r1,
                                     unsigned& r2, unsigned& r3) {
    asm volatile("ldmatrix.sync.aligned.m8n8.x4.shared.b16 {%0,%1,%2,%3}, [%4];"
                 : "=r"(r0), "=r"(r1), "=r"(r2), "=r"(r3) : "r"(addr));
}
__device__ __forceinline__ void ldm4t(unsigned addr, unsigned& r0, unsigned& r1,
                                      unsigned& r2, unsigned& r3) {
    asm volatile("ldmatrix.sync.aligned.m8n8.x4.trans.shared.b16 {%0,%1,%2,%3}, [%4];"
                 : "=r"(r0), "=r"(r1), "=r"(r2), "=r"(r3) : "r"(addr));
}
__device__ __forceinline__ unsigned packh(const __half* p0, const __half* p1) {
    unsigned lo = *(const unsigned short*)p0;
    unsigned hi = *(const unsigned short*)p1;
    return lo | (hi << 16);
}

// ---------------------------------------------------------------------------
// Prep: base_feat -> fp16; weights -> fp16 (tap-major for w_c1; packed head).
// ---------------------------------------------------------------------------
#define PREP_N4 4194304             // (8*512*4096)/4, float4 granularity
#define PREP_N1 262144              // 512*512
#define PREP_N2 442368              // 9*384*128
#define PREP_N3 24576               // 64*384
#define PREP_TOT (PREP_N4 + PREP_N1 + PREP_N2 + PREP_N3)

__global__ void k_prep(const float* __restrict__ base_feat,
                       const float* __restrict__ w_f, const float* __restrict__ w_2,
                       const float* __restrict__ w_c1,
                       const float* __restrict__ w_cls, const float* __restrict__ w_box)
{
    int i = blockIdx.x * 256 + threadIdx.x;
    if (i < PREP_N4) {
        float4 v = ((const float4*)base_feat)[i];
        __half2* dst = (__half2*)(g_bfh + (size_t)i * 4);
        dst[0] = __floats2half2_rn(v.x, v.y);
        dst[1] = __floats2half2_rn(v.z, v.w);
        return;
    }
    i -= PREP_N4;
    if (i < PREP_N1) {
        int m = i >> 9;
        float v = (m < 128) ? w_f[i] : w_2[i - 65536];
        g_wah[i] = __float2half_rn(v);
        return;
    }
    i -= PREP_N1;
    if (i < PREP_N2) {
        int tap = i / 49152, rem = i % 49152;
        int m = rem >> 7, c = rem & 127;
        g_wth[i] = __float2half_rn(w_c1[(size_t)m * 1152 + c * 9 + tap]);
        return;
    }
    i -= PREP_N2;
    if (i < PREP_N3) {
        int r = i / 384, k = i - r * 384;
        float v;
        if (r < 18)      v = w_cls[i];
        else if (r < 54) v = w_box[(r - 18) * 384 + k];
        else             v = 0.f;
        g_whh[i] = __float2half_rn(v);
    }
}

// ---------------------------------------------------------------------------
// Kernel 1: fused 1x1 conv 512 -> 512, ReLU -> d_out feat region.
// fp16 m16n8k16 MMA, ldmatrix fragments. 4 warps of 64x64, 128 thr.
// Stage = K16: A [128][24]h (48B rows, conflict-free), B [16][136]h (272B
// rows, conflict-free). 4-stage ring, 1 commit + wait1 + sync per stage.
// Ping-pong fragment sets: ldm(stage t+1) overlaps mma(stage t).
// mt==0 also writes fp16 channels 0..127 to g_feath.
// ---------------------------------------------------------------------------
#define C1_A_B  6144
#define C1_B_B  4352
#define C1_ST_B (C1_A_B + C1_B_B)   // 10496
#define C1_SMEM (4 * C1_ST_B)       // 41984

__global__ __launch_bounds__(128, 2)
void k_conv1(const float* __restrict__ b_f, const float* __restrict__ b_2,
             float* __restrict__ out)
{
    extern __shared__ char ds[];
    const int n  = blockIdx.z;
    const int mt = blockIdx.y;
    const int n0 = blockIdx.x * 128;
    const int mtb = mt * 128;
    const float* bi = (mt == 0) ? b_f : (b_2 + (mt - 1) * 128);
    const __half* Bp = g_bfh + (size_t)n * CIN * HW + n0;

    const int tid  = threadIdx.x;
    const int warp = tid >> 5, lane = tid & 31;
    const int wm = (warp >> 1) * 64, wn = (warp & 1) * 64;
    const int g  = lane >> 2, t4 = lane & 3;
    const int l15 = lane & 15, l16 = lane >> 4;

    auto loadT = [&](int s) {
        if (s < 32) {
            char* As = ds + (s & 3) * C1_ST_B;
            char* Bs = As + C1_A_B;
            const int k0 = s * 16;
            #pragma unroll
            for (int j = 0; j < 2; j++) {
                int e = tid + j * 128;
                int row = e >> 1, sub = e & 1;
                cp16(sptr(As + row * 48 + sub * 16),
                     g_wah + (size_t)(mtb + row) * 512 + k0 + sub * 8, true);
                int brow = e >> 4, xu = e & 15;
                cp16(sptr(Bs + brow * 272 + xu * 16),
                     Bp + (size_t)(k0 + brow) * HW + xu * 8, true);
            }
        }
        cpcommit();
    };

    auto ldmAB = [&](int s, unsigned (&a)[4][4], unsigned (&b)[8][2]) {
        const char* As = ds + (s & 3) * C1_ST_B;
        const char* Bs = As + C1_A_B;
        #pragma unroll
        for (int mf = 0; mf < 4; mf++) {
            unsigned addr = sptr(As) + (wm + mf * 16 + l15) * 48 + l16 * 16;
            ldm4(addr, a[mf][0], a[mf][1], a[mf][2], a[mf][3]);
        }
        #pragma unroll
        for (int p = 0; p < 4; p++) {
            unsigned addr = sptr(Bs) + l15 * 272 + (wn + p * 16 + l16 * 8) * 2;
            ldm4t(addr, b[2*p][0], b[2*p][1], b[2*p+1][0], b[2*p+1][1]);
        }
    };

    float acc[4][8][4] = {};
    unsigned aA[4][4], bA[8][2], aB[4][4], bB[8][2];

    loadT(0); loadT(1); loadT(2);
    cpwait1();                                  // stages 0,1 done
    __syncthreads();
    ldmAB(0, aA, bA);

    for (int u = 0; u < 16; u++) {
        const int t0 = 2 * u;
        if (t0) { cpwait1(); __syncthreads(); }
        loadT(t0 + 3);
        ldmAB(t0 + 1, aB, bB);
        #pragma unroll
        for (int mf = 0; mf < 4; mf++)
            #pragma unroll
            for (int nf = 0; nf < 8; nf++) mma16(acc[mf][nf], aA[mf], bA[nf]);

        cpwait1(); __syncthreads();
        loadT(t0 + 4);
        if (t0 + 2 < 32) ldmAB(t0 + 2, aA, bA);
        #pragma unroll
        for (int mf = 0; mf < 4; mf++)
            #pragma unroll
            for (int nf = 0; nf < 8; nf++) mma16(acc[mf][nf], aB[mf], bB[nf]);
    }

    float*  outb = out + (size_t)n * CIN * HW + (size_t)mt * 128 * HW;
    __half* fh   = g_feath + (size_t)n * 128 * HW;
    #pragma unroll
    for (int mf = 0; mf < 4; mf++) {
        int r0 = wm + mf * 16 + g;
        float bv0 = bi[r0], bv1 = bi[r0 + 8];
        #pragma unroll
        for (int nf = 0; nf < 8; nf++) {
            int c = n0 + wn + nf * 8 + t4 * 2;
            float2 v0, v1;
            v0.x = fmaxf(acc[mf][nf][0] + bv0, 0.f);
            v0.y = fmaxf(acc[mf][nf][1] + bv0, 0.f);
            v1.x = fmaxf(acc[mf][nf][2] + bv1, 0.f);
            v1.y = fmaxf(acc[mf][nf][3] + bv1, 0.f);
            *(float2*)(outb + (size_t)r0 * HW + c)       = v0;
            *(float2*)(outb + (size_t)(r0 + 8) * HW + c) = v1;
            if (mt == 0) {
                *(__half2*)(fh + (size_t)r0 * HW + c)       = __floats2half2_rn(v0.x, v0.y);
                *(__half2*)(fh + (size_t)(r0 + 8) * HW + c) = __floats2half2_rn(v1.x, v1.y);
            }
        }
    }
}

// ---------------------------------------------------------------------------
// Kernel 2: 3x3 conv 128 -> 384 pad=1, ReLU -> g_rpn1h (fp16).
// fp16 m16n8k16 MMA. A (weights) via ldmatrix from 4-stage ring; B from fp16
// halo tiles (shifted views are 2B-misaligned -> scalar u16-pair loads+pack).
// 72 (kc,tap) stages; H(kc) bundled into stage-9kc commit group; 2 H buffers.
// H slice: [8 zero pad halves][4 rows of 72], cols 64..71 zeroed.
// ---------------------------------------------------------------------------
#define H_ROWH   72
#define H_PADH   8
#define H_SLICEH 296
#define H_BUFH   (16 * H_SLICEH)
#define C3_A_B   6144
#define C3_SMEM  (4 * C3_A_B + 2 * H_BUFH * 2)   // 24576 + 18944 = 43520

__global__ __launch_bounds__(128, 2)
void k_conv3(const float* __restrict__ b_c1)
{
    extern __shared__ char ds[];
    __half* Hbh = (__half*)(ds + 4 * C3_A_B);

    const int n  = blockIdx.z;
    const int m0 = blockIdx.y * 128;
    const int n0 = blockIdx.x * 128;
    const int y0 = blockIdx.x * 2;

    const int tid  = threadIdx.x;
    const int warp = tid >> 5, lane = tid & 31;
    const int wm = (warp >> 1) * 64, wn = (warp & 1) * 64;
    const int g  = lane >> 2, t4 = lane & 3;
    const int l15 = lane & 15, l16 = lane >> 4;

    // zero pads: per (buf,k): front 8 halves + halo cols 64..71 of 4 rows
    for (int i = tid; i < 1280; i += 128) {
        int buf = i / 640, r2 = i % 640;
        int k = r2 / 40, e = r2 % 40;
        int off = (e < 8) ? e
                          : H_PADH + ((e - 8) >> 3) * H_ROWH + 64 + ((e - 8) & 7);
        Hbh[buf * H_BUFH + k * H_SLICEH + off] = __float2half(0.f);
    }

    auto loadH = [&](int kc, int buf) {
        #pragma unroll
        for (int j = 0; j < 4; j++) {
            int e = tid + j * 128;                 // 0..511
            int k = e >> 5, rem = e & 31, r = rem >> 3, xu = rem & 7;
            int gy = y0 - 1 + r;
            cp16(sptr(Hbh + buf * H_BUFH + k * H_SLICEH + H_PADH + r * H_ROWH + xu * 8),
                 g_feath + (size_t)n * 128 * HW + (size_t)(kc * 16 + k) * HW + gy * 64 + xu * 8,
                 (unsigned)gy < 64u);
        }
    };
    auto loadT = [&](int s) {
        if (s < 72) {
            int kc = s / 9, tap = s - kc * 9;
            char* As = ds + (s & 3) * C3_A_B;
            #pragma unroll
            for (int j = 0; j < 2; j++) {
                int e = tid + j * 128;
                int row = e >> 1, sub = e & 1;
                cp16(sptr(As + row * 48 + sub * 16),
                     g_wth + ((size_t)tap * 384 + m0 + row) * 128 + kc * 16 + sub * 8, true);
            }
            if (tap == 0 && kc < 8) loadH(kc, kc & 1);
        }
        cpcommit();
    };

    int ib[8];
    #pragma unroll
    for (int nf = 0; nf < 8; nf++) {
        int px = wn + nf * 8 + g;
        ib[nf] = H_PADH + (1 + (px >> 6)) * H_ROWH + (px & 63);
    }

    auto ldfr = [&](int s, unsigned (&a)[4][4], unsigned (&b)[8][2]) {
        int kc = s / 9, tap = s - kc * 9;
        int hoff = (tap / 3 - 1) * H_ROWH + (tap % 3 - 1);
        const char* As = ds + (s & 3) * C3_A_B;
        const __half* Hc = Hbh + (kc & 1) * H_BUFH;
        #pragma unroll
        for (int mf = 0; mf < 4; mf++) {
            unsigned addr = sptr(As) + (wm + mf * 16 + l15) * 48 + l16 * 16;
            ldm4(addr, a[mf][0], a[mf][1], a[mf][2], a[mf][3]);
        }
        const __half* r0 = Hc + (2 * t4) * H_SLICEH + hoff;
        const __half* r1 = r0 + H_SLICEH;
        const __half* r8 = r0 + 8 * H_SLICEH;
        const __half* r9 = r8 + H_SLICEH;
        #pragma unroll
        for (int nf = 0; nf < 8; nf++) {
            int idx = ib[nf];
            b[nf][0] = packh(r0 + idx, r1 + idx);
            b[nf][1] = packh(r8 + idx, r9 + idx);
        }
    };

    float acc[4][8][4] = {};
    unsigned aA[4][4], bA[8][2], aB[4][4], bB[8][2];

    loadT(0); loadT(1); loadT(2);    // stage0 group includes H(0)
    cpwait1();
    __syncthreads();                 // pads + stages 0,1 visible
    ldfr(0, aA, bA);

    for (int u = 0; u < 36; u++) {
        const int t0 = 2 * u;
        if (t0) { cpwait1(); __syncthreads(); }
        loadT(t0 + 3);
        ldfr(t0 + 1, aB, bB);
        #pragma unroll
        for (int mf = 0; mf < 4; mf++)
            #pragma unroll
            for (int nf = 0; nf < 8; nf++) mma16(acc[mf][nf], aA[mf], bA[nf]);

        cpwait1(); __syncthreads();
        loadT(t0 + 4);
        if (t0 + 2 < 72) ldfr(t0 + 2, aA, bA);
        #pragma unroll
        for (int mf = 0; mf < 4; mf++)
            #pragma unroll
            for (int nf = 0; nf < 8; nf++) mma16(acc[mf][nf], aB[mf], bB[nf]);
    }

    __half* ob = g_rpn1h + (size_t)n * 384 * HW;
    #pragma unroll
    for (int mf = 0; mf < 4; mf++) {
        int r0 = m0 + wm + mf * 16 + g;
        float bv0 = b_c1[r0], bv1 = b_c1[r0 + 8];
        #pragma unroll
        for (int nf = 0; nf < 8; nf++) {
            int c = n0 + wn + nf * 8 + t4 * 2;
            float x0 = fmaxf(acc[mf][nf][0] + bv0, 0.f);
            float x1 = fmaxf(acc[mf][nf][1] + bv0, 0.f);
            float x2 = fmaxf(acc[mf][nf][2] + bv1, 0.f);
            float x3 = fmaxf(acc[mf][nf][3] + bv1, 0.f);
            *(__half2*)(ob + (size_t)r0 * HW + c)       = __floats2half2_rn(x0, x1);
            *(__half2*)(ob + (size_t)(r0 + 8) * HW + c) = __floats2half2_rn(x2, x3);
        }
    }
}

// ---------------------------------------------------------------------------
// Kernel 3: head. fp16 MMA + full ldmatrix. 4 warps of 32x64, 128 thr.
// 24 K16 stages, 4-stage ring. Bias + paired softmax (c, c+9) for cls,
// bias for box, two zero scalars. Cs overlay needs 33792B.
// ---------------------------------------------------------------------------
#define HD_A_B  3072
#define HD_B_B  4352
#define HD_ST_B (HD_A_B + HD_B_B)   // 7424
#define HD_SMEM 34048               // max(4*7424=29696, Cs 33792) + pad

__global__ __launch_bounds__(128)
void k_head(const float* __restrict__ b_cls, const float* __restrict__ b_box,
            float* __restrict__ out)
{
    extern __shared__ char ds[];
    const int n  = blockIdx.z;
    const int n0 = blockIdx.x * 128;
    const __half* Bp = g_rpn1h + (size_t)n * 384 * HW + n0;

    const int tid  = threadIdx.x;
    const int warp = tid >> 5, lane = tid & 31;
    const int wm = (warp >> 1) * 32, wn = (warp & 1) * 64;
    const int g  = lane >> 2, t4 = lane & 3;
    const int l15 = lane & 15, l16 = lane >> 4;

    auto loadT = [&](int s) {
        if (s < 24) {
            char* As = ds + (s & 3) * HD_ST_B;
            char* Bs = As + HD_A_B;
            const int k0 = s * 16;
            {
                int row = tid >> 1, sub = tid & 1;  // 128 chunks
                cp16(sptr(As + row * 48 + sub * 16),
                     g_whh + (size_t)row * 384 + k0 + sub * 8, true);
            }
            #pragma unroll
            for (int j = 0; j < 2; j++) {
                int e = tid + j * 128;
                int row = e >> 4, xu = e & 15;
                cp16(sptr(Bs + row * 272 + xu * 16),
                     Bp + (size_t)(k0 + row) * HW + xu * 8, true);
            }
        }
        cpcommit();
    };

    auto ldmAB = [&](int s, unsigned (&a)[2][4], unsigned (&b)[8][2]) {
        const char* As = ds + (s & 3) * HD_ST_B;
        const char* Bs = As + HD_A_B;
        #pragma unroll
        for (int mf = 0; mf < 2; mf++) {
            unsigned addr = sptr(As) + (wm + mf * 16 + l15) * 48 + l16 * 16;
            ldm4(addr, a[mf][0], a[mf][1], a[mf][2], a[mf][3]);
        }
        #pragma unroll
        for (int p = 0; p < 4; p++) {
            unsigned addr = sptr(Bs) + l15 * 272 + (wn + p * 16 + l16 * 8) * 2;
            ldm4t(addr, b[2*p][0], b[2*p][1], b[2*p+1][0], b[2*p+1][1]);
        }
    };

    float acc[2][8][4] = {};
    unsigned aA[2][4], bA[8][2], aB[2][4], bB[8][2];

    loadT(0); loadT(1); loadT(2);
    cpwait1();
    __syncthreads();
    ldmAB(0, aA, bA);

    for (int u = 0; u < 12; u++) {
        const int t0 = 2 * u;
        if (t0) { cpwait1(); __syncthreads(); }
        loadT(t0 + 3);
        ldmAB(t0 + 1, aB, bB);
        #pragma unroll
        for (int mf = 0; mf < 2; mf++)
            #pragma unroll
            for (int nf = 0; nf < 8; nf++) mma16(acc[mf][nf], aA[mf], bA[nf]);

        cpwait1(); __syncthreads();
        loadT(t0 + 4);
        if (t0 + 2 < 24) ldmAB(t0 + 2, aA, bA);
        #pragma unroll
        for (int mf = 0; mf < 2; mf++)
            #pragma unroll
            for (int nf = 0; nf < 8; nf++) mma16(acc[mf][nf], aB[mf], bB[nf]);
    }

    __syncthreads();                       // all warps done reading ring
    float (*Cs)[132] = (float(*)[132])ds;  // overlay
    #pragma unroll
    for (int mf = 0; mf < 2; mf++) {
        int r0 = wm + mf * 16 + g;
        #pragma unroll
        for (int nf = 0; nf < 8; nf++) {
            int c = wn + nf * 8 + t4 * 2;
            Cs[r0][c]         = acc[mf][nf][0];
            Cs[r0][c + 1]     = acc[mf][nf][1];
            Cs[r0 + 8][c]     = acc[mf][nf][2];
            Cs[r0 + 8][c + 1] = acc[mf][nf][3];
        }
    }
    __syncthreads();

    const size_t F1 = (size_t)CB * CIN * HW;
    const size_t F2 = F1 + (size_t)CB * 18 * HW;
    const size_t F3 = F2 + (size_t)CB * 36 * HW;

    for (int it = tid; it < 9 * 128; it += 128) {
        int c = it >> 7, j = it & 127;
        float s0 = Cs[c][j]     + b_cls[c];
        float s1 = Cs[c + 9][j] + b_cls[c + 9];
        float m  = fmaxf(s0, s1);
        float e0 = expf(s0 - m), e1 = expf(s1 - m);
        float inv = 1.f / (e0 + e1);
        out[F1 + (size_t)n * 18 * HW + (size_t)c * HW + n0 + j]       = e0 * inv;
        out[F1 + (size_t)n * 18 * HW + (size_t)(c + 9) * HW + n0 + j] = e1 * inv;
    }
    for (int it = tid; it < 36 * 128; it += 128) {
        int c = it >> 7, j = it & 127;
        out[F2 + (size_t)n * 36 * HW + (size_t)c * HW + n0 + j] = Cs[18 + c][j] + b_box[c];
    }
    if (n == 0 && blockIdx.x == 0 && tid == 0) {
        out[F3]     = 0.f;
        out[F3 + 1] = 0.f;
    }
}

// ---------------------------------------------------------------------------
extern "C" void kernel_launch(void* const* d_in, const int* in_sizes, int n_in,
                              void* d_out, int out_size)
{
    const float* base  = (const float*)d_in[0];
    const float* w_f   = (const float*)d_in[3];
    const float* b_f   = (const float*)d_in[4];
    const float* w_2   = (const float*)d_in[5];
    const float* b_2   = (const float*)d_in[6];
    const float* w_c1  = (const float*)d_in[7];
    const float* b_c1  = (const float*)d_in[8];
    const float* w_cls = (const float*)d_in[9];
    const float* b_cls = (const float*)d_in[10];
    const float* w_box = (const float*)d_in[11];
    const float* b_box = (const float*)d_in[12];
    float* out = (float*)d_out;

    static bool attr_set = false;
    if (!attr_set) {
        cudaFuncSetAttribute(k_conv1, cudaFuncAttributeMaxDynamicSharedMemorySize, C1_SMEM);
        cudaFuncSetAttribute(k_conv3, cudaFuncAttributeMaxDynamicSharedMemorySize, C3_SMEM);
        cudaFuncSetAttribute(k_head,  cudaFuncAttributeMaxDynamicSharedMemorySize, HD_SMEM);
        attr_set = true;
    }

    k_prep <<<(PREP_TOT + 255) / 256, 256>>>(base, w_f, w_2, w_c1, w_cls, w_box);
    k_conv1<<<dim3(32, 4, CB), 128, C1_SMEM>>>(b_f, b_2, out);
    k_conv3<<<dim3(32, 3, CB), 128, C3_SMEM>>>(b_c1);
    k_head <<<dim3(32, 1, CB), 128, HD_SMEM>>>(b_cls, b_box, out);
}

// round 13
// speedup vs baseline: 1.5102x; 1.0254x over previous
#include <cuda_runtime.h>
#include <cuda_fp16.h>
#include <cstdint>

// Problem constants
#define CB   8
#define HW   4096          // 64*64
#define CIN  512

// Device scratch (fp16: same 11-bit significand as tf32)
static __device__ __half  g_bfh[(size_t)CB * 512 * HW];   // base_feat fp16 (32MB)
static __device__ __half  g_rpn1h[(size_t)CB * 384 * HW]; // conv3 out (24MB)
static __device__ __half2 g_feath2[(size_t)CB * 64 * HW]; // convf_rpn pair-interleaved (8MB)
static __device__ __half  g_wah[512 * 512];               // [w_f; w_2]
static __device__ __half  g_wth[9 * 384 * 128];           // w_c1 tap-major
static __device__ __half  g_whh[64 * 384];                // [w_cls; w_box; 0]

// ---------------------------------------------------------------------------
// helpers
// ---------------------------------------------------------------------------
__device__ __forceinline__ void mma16(float d[4], const unsigned a[4], const unsigned b[2]) {
    asm volatile(
        "mma.sync.aligned.m16n8k16.row.col.f32.f16.f16.f32 "
        "{%0,%1,%2,%3}, {%4,%5,%6,%7}, {%8,%9}, {%0,%1,%2,%3};\n"
        : "+f"(d[0]), "+f"(d[1]), "+f"(d[2]), "+f"(d[3])
        : "r"(a[0]), "r"(a[1]), "r"(a[2]), "r"(a[3]), "r"(b[0]), "r"(b[1]));
}

__device__ __forceinline__ unsigned sptr(const void* p) {
    return (unsigned)__cvta_generic_to_shared(p);
}
__device__ __forceinline__ void cp16(unsigned d, const void* s, bool ok) {
    asm volatile("cp.async.cg.shared.global [%0], [%1], 16, %2;\n"
                 :: "r"(d), "l"(s), "r"(ok ? 16 : 0));
}
__device__ __forceinline__ void cpcommit() { asm volatile("cp.async.commit_group;\n"); }
__device__ __forceinline__ void cpwait1()  { asm volatile("cp.async.wait_group 1;\n"); }

__device__ __forceinline__ void ldm4(unsigned addr, unsigned& r0, unsigned& r1,
                                     unsigned& r2, unsigned& r3) {
    asm volatile("ldmatrix.sync.aligned.m8n8.x4.shared.b16 {%0,%1,%2,%3}, [%4];"
                 : "=r"(r0), "=r"(r1), "=r"(r2), "=r"(r3) : "r"(addr));
}
__device__ __forceinline__ void ldm4t(unsigned addr, unsigned& r0, unsigned& r1,
                                      unsigned& r2, unsigned& r3) {
    asm volatile("ldmatrix.sync.aligned.m8n8.x4.trans.shared.b16 {%0,%1,%2,%3}, [%4];"
                 : "=r"(r0), "=r"(r1), "=r"(r2), "=r"(r3) : "r"(addr));
}

// ---------------------------------------------------------------------------
// Prep: base_feat -> fp16; weights -> fp16 (tap-major for w_c1; packed head).
// ---------------------------------------------------------------------------
#define PREP_N4 4194304             // (8*512*4096)/4, float4 granularity
#define PREP_N1 262144              // 512*512
#define PREP_N2 442368              // 9*384*128
#define PREP_N3 24576               // 64*384
#define PREP_TOT (PREP_N4 + PREP_N1 + PREP_N2 + PREP_N3)

__global__ void k_prep(const float* __restrict__ base_feat,
                       const float* __restrict__ w_f, const float* __restrict__ w_2,
                       const float* __restrict__ w_c1,
                       const float* __restrict__ w_cls, const float* __restrict__ w_box)
{
    int i = blockIdx.x * 256 + threadIdx.x;
    if (i < PREP_N4) {
        float4 v = ((const float4*)base_feat)[i];
        __half2* dst = (__half2*)(g_bfh + (size_t)i * 4);
        dst[0] = __floats2half2_rn(v.x, v.y);
        dst[1] = __floats2half2_rn(v.z, v.w);
        return;
    }
    i -= PREP_N4;
    if (i < PREP_N1) {
        int m = i >> 9;
        float v = (m < 128) ? w_f[i] : w_2[i - 65536];
        g_wah[i] = __float2half_rn(v);
        return;
    }
    i -= PREP_N1;
    if (i < PREP_N2) {
        int tap = i / 49152, rem = i % 49152;
        int m = rem >> 7, c = rem & 127;
        g_wth[i] = __float2half_rn(w_c1[(size_t)m * 1152 + c * 9 + tap]);
        return;
    }
    i -= PREP_N2;
    if (i < PREP_N3) {
        int r = i / 384, k = i - r * 384;
        float v;
        if (r < 18)      v = w_cls[i];
        else if (r < 54) v = w_box[(r - 18) * 384 + k];
        else             v = 0.f;
        g_whh[i] = __float2half_rn(v);
    }
}

// ---------------------------------------------------------------------------
// Kernel 1: fused 1x1 conv 512 -> 512, ReLU -> d_out feat region.
// fp16 m16n8k16 MMA, ldmatrix fragments. 4 warps of 64x64, 128 thr.
// 4-stage K16 ring. mt==0 also writes PAIR-INTERLEAVED fp16 channels
// 0..127 to g_feath2 (channel pair 2k2,2k2+1 packed per pixel) via two
// lane shuffles (partner lane+4 holds channel r0+1).
// ---------------------------------------------------------------------------
#define C1_A_B  6144
#define C1_B_B  4352
#define C1_ST_B (C1_A_B + C1_B_B)   // 10496
#define C1_SMEM (4 * C1_ST_B)       // 41984

__global__ __launch_bounds__(128, 2)
void k_conv1(const float* __restrict__ b_f, const float* __restrict__ b_2,
             float* __restrict__ out)
{
    extern __shared__ char ds[];
    const int n  = blockIdx.z;
    const int mt = blockIdx.y;
    const int n0 = blockIdx.x * 128;
    const int mtb = mt * 128;
    const float* bi = (mt == 0) ? b_f : (b_2 + (mt - 1) * 128);
    const __half* Bp = g_bfh + (size_t)n * CIN * HW + n0;

    const int tid  = threadIdx.x;
    const int warp = tid >> 5, lane = tid & 31;
    const int wm = (warp >> 1) * 64, wn = (warp & 1) * 64;
    const int g  = lane >> 2, t4 = lane & 3;
    const int l15 = lane & 15, l16 = lane >> 4;

    auto loadT = [&](int s) {
        if (s < 32) {
            char* As = ds + (s & 3) * C1_ST_B;
            char* Bs = As + C1_A_B;
            const int k0 = s * 16;
            #pragma unroll
            for (int j = 0; j < 2; j++) {
                int e = tid + j * 128;
                int row = e >> 1, sub = e & 1;
                cp16(sptr(As + row * 48 + sub * 16),
                     g_wah + (size_t)(mtb + row) * 512 + k0 + sub * 8, true);
                int brow = e >> 4, xu = e & 15;
                cp16(sptr(Bs + brow * 272 + xu * 16),
                     Bp + (size_t)(k0 + brow) * HW + xu * 8, true);
            }
        }
        cpcommit();
    };

    auto ldmAB = [&](int s, unsigned (&a)[4][4], unsigned (&b)[8][2]) {
        const char* As = ds + (s & 3) * C1_ST_B;
        const char* Bs = As + C1_A_B;
        #pragma unroll
        for (int mf = 0; mf < 4; mf++) {
            unsigned addr = sptr(As) + (wm + mf * 16 + l15) * 48 + l16 * 16;
            ldm4(addr, a[mf][0], a[mf][1], a[mf][2], a[mf][3]);
        }
        #pragma unroll
        for (int p = 0; p < 4; p++) {
            unsigned addr = sptr(Bs) + l15 * 272 + (wn + p * 16 + l16 * 8) * 2;
            ldm4t(addr, b[2*p][0], b[2*p][1], b[2*p+1][0], b[2*p+1][1]);
        }
    };

    float acc[4][8][4] = {};
    unsigned aA[4][4], bA[8][2], aB[4][4], bB[8][2];

    loadT(0); loadT(1); loadT(2);
    cpwait1();
    __syncthreads();
    ldmAB(0, aA, bA);

    for (int u = 0; u < 16; u++) {
        const int t0 = 2 * u;
        if (t0) { cpwait1(); __syncthreads(); }
        loadT(t0 + 3);
        ldmAB(t0 + 1, aB, bB);
        #pragma unroll
        for (int mf = 0; mf < 4; mf++)
            #pragma unroll
            for (int nf = 0; nf < 8; nf++) mma16(acc[mf][nf], aA[mf], bA[nf]);

        cpwait1(); __syncthreads();
        loadT(t0 + 4);
        if (t0 + 2 < 32) ldmAB(t0 + 2, aA, bA);
        #pragma unroll
        for (int mf = 0; mf < 4; mf++)
            #pragma unroll
            for (int nf = 0; nf < 8; nf++) mma16(acc[mf][nf], aB[mf], bB[nf]);
    }

    float*   outb = out + (size_t)n * CIN * HW + (size_t)mt * 128 * HW;
    __half2* gf2  = g_feath2 + (size_t)n * 64 * HW;
    #pragma unroll
    for (int mf = 0; mf < 4; mf++) {
        int r0 = wm + mf * 16 + g;
        float bv0 = bi[r0], bv1 = bi[r0 + 8];
        #pragma unroll
        for (int nf = 0; nf < 8; nf++) {
            int c = n0 + wn + nf * 8 + t4 * 2;
            float2 v0, v1;
            v0.x = fmaxf(acc[mf][nf][0] + bv0, 0.f);
            v0.y = fmaxf(acc[mf][nf][1] + bv0, 0.f);
            v1.x = fmaxf(acc[mf][nf][2] + bv1, 0.f);
            v1.y = fmaxf(acc[mf][nf][3] + bv1, 0.f);
            *(float2*)(outb + (size_t)r0 * HW + c)       = v0;
            *(float2*)(outb + (size_t)(r0 + 8) * HW + c) = v1;
            if (mt == 0) {
                // pair-interleave: partner lane+4 holds channel r0+1
                float p0x = __shfl_down_sync(0xffffffffu, v0.x, 4);
                float p0y = __shfl_down_sync(0xffffffffu, v0.y, 4);
                float p1x = __shfl_down_sync(0xffffffffu, v1.x, 4);
                float p1y = __shfl_down_sync(0xffffffffu, v1.y, 4);
                if (!(g & 1)) {
                    __half2* d0 = gf2 + (size_t)(r0 >> 1) * HW + c;
                    d0[0] = __floats2half2_rn(v0.x, p0x);
                    d0[1] = __floats2half2_rn(v0.y, p0y);
                    __half2* d1 = gf2 + (size_t)((r0 >> 1) + 4) * HW + c;
                    d1[0] = __floats2half2_rn(v1.x, p1x);
                    d1[1] = __floats2half2_rn(v1.y, p1y);
                }
            }
        }
    }
}

// ---------------------------------------------------------------------------
// Kernel 2: 3x3 conv 128 -> 384 pad=1, ReLU -> g_rpn1h (fp16).
// fp16 m16n8k16. A via ldmatrix from 4-stage ring. B from PAIR-INTERLEAVED
// halo tiles: each b-register = ONE aligned LDS.32 (__half2 = channel pair
// at a pixel); dx shift = +-1 __half2 = 4B, stays aligned. H2 slice per k2:
// [4 zero-pad __half2][4 rows x 68 __half2], cols 64..67 zeroed; slice
// stride 280 (banks 24*t4+g -> conflict-free). 2 H buffers at kc cadence.
// ---------------------------------------------------------------------------
#define H2_ROW   68
#define H2_PAD   4
#define H2_SLICE 280                // __half2 units (1120B, 16B-divisible)
#define H2_BUF   (8 * H2_SLICE)     // 2240 __half2 per buffer (8960B)
#define C3_A_B   6144
#define C3_SMEM  (4 * C3_A_B + 2 * H2_BUF * 4)   // 24576 + 17920 = 42496

__global__ __launch_bounds__(128, 2)
void k_conv3(const float* __restrict__ b_c1)
{
    extern __shared__ char ds[];
    __half2* Hb2 = (__half2*)(ds + 4 * C3_A_B);

    const int n  = blockIdx.z;
    const int m0 = blockIdx.y * 128;
    const int n0 = blockIdx.x * 128;
    const int y0 = blockIdx.x * 2;

    const int tid  = threadIdx.x;
    const int warp = tid >> 5, lane = tid & 31;
    const int wm = (warp >> 1) * 64, wn = (warp & 1) * 64;
    const int g  = lane >> 2, t4 = lane & 3;
    const int l15 = lane & 15, l16 = lane >> 4;

    // zero pads: per (buf,k2): front 4 __half2 + halo cols 64..67 of 4 rows
    // = 20 __half2; total 2*8*20 = 320
    for (int i = tid; i < 320; i += 128) {
        int buf = i / 160, r2 = i % 160;
        int k2 = r2 / 20, e = r2 % 20;
        int off = (e < 4) ? e
                          : H2_PAD + ((e - 4) >> 2) * H2_ROW + 64 + ((e - 4) & 3);
        Hb2[buf * H2_BUF + k2 * H2_SLICE + off] = __floats2half2_rn(0.f, 0.f);
    }

    auto loadH = [&](int kc, int buf) {
        const __half2* src = g_feath2 + (size_t)n * 64 * HW;
        #pragma unroll
        for (int j = 0; j < 4; j++) {
            int e = tid + j * 128;                 // 0..511
            int k2 = e >> 6, rem = e & 63, r = rem >> 4, xu = rem & 15;
            int gy = y0 - 1 + r;
            cp16(sptr(Hb2 + buf * H2_BUF + k2 * H2_SLICE + H2_PAD + r * H2_ROW + xu * 4),
                 src + (size_t)(kc * 8 + k2) * HW + gy * 64 + xu * 4,
                 (unsigned)gy < 64u);
        }
    };
    auto loadT = [&](int s) {
        if (s < 72) {
            int kc = s / 9, tap = s - kc * 9;
            char* As = ds + (s & 3) * C3_A_B;
            #pragma unroll
            for (int j = 0; j < 2; j++) {
                int e = tid + j * 128;
                int row = e >> 1, sub = e & 1;
                cp16(sptr(As + row * 48 + sub * 16),
                     g_wth + ((size_t)tap * 384 + m0 + row) * 128 + kc * 16 + sub * 8, true);
            }
            if (tap == 0 && kc < 8) loadH(kc, kc & 1);
        }
        cpcommit();
    };

    // per-thread pixel base offsets into an H2 slice (center row = 1 + px>>6)
    int ib2[8];
    #pragma unroll
    for (int nf = 0; nf < 8; nf++) {
        int px = wn + nf * 8 + g;
        ib2[nf] = H2_PAD + (1 + (px >> 6)) * H2_ROW + (px & 63);
    }

    auto ldfr = [&](int s, unsigned (&a)[4][4], unsigned (&b)[8][2]) {
        int kc = s / 9, tap = s - kc * 9;
        int hoff = (tap / 3 - 1) * H2_ROW + (tap % 3 - 1);
        const char* As = ds + (s & 3) * C3_A_B;
        const __half2* Hc = Hb2 + (kc & 1) * H2_BUF;
        #pragma unroll
        for (int mf = 0; mf < 4; mf++) {
            unsigned addr = sptr(As) + (wm + mf * 16 + l15) * 48 + l16 * 16;
            ldm4(addr, a[mf][0], a[mf][1], a[mf][2], a[mf][3]);
        }
        const __half2* s0 = Hc + t4 * H2_SLICE + hoff;        // pair t4   (k=2t4,2t4+1)
        const __half2* s1 = Hc + (t4 + 4) * H2_SLICE + hoff;  // pair t4+4 (k=8+2t4,...)
        #pragma unroll
        for (int nf = 0; nf < 8; nf++) {
            b[nf][0] = *(const unsigned*)(s0 + ib2[nf]);
            b[nf][1] = *(const unsigned*)(s1 + ib2[nf]);
        }
    };

    float acc[4][8][4] = {};
    unsigned aA[4][4], bA[8][2], aB[4][4], bB[8][2];

    loadT(0); loadT(1); loadT(2);    // stage0 group includes H(0)
    cpwait1();
    __syncthreads();                 // pads + stages 0,1 visible
    ldfr(0, aA, bA);

    for (int u = 0; u < 36; u++) {
        const int t0 = 2 * u;
        if (t0) { cpwait1(); __syncthreads(); }
        loadT(t0 + 3);
        ldfr(t0 + 1, aB, bB);
        #pragma unroll
        for (int mf = 0; mf < 4; mf++)
            #pragma unroll
            for (int nf = 0; nf < 8; nf++) mma16(acc[mf][nf], aA[mf], bA[nf]);

        cpwait1(); __syncthreads();
        loadT(t0 + 4);
        if (t0 + 2 < 72) ldfr(t0 + 2, aA, bA);
        #pragma unroll
        for (int mf = 0; mf < 4; mf++)
            #pragma unroll
            for (int nf = 0; nf < 8; nf++) mma16(acc[mf][nf], aB[mf], bB[nf]);
    }

    __half* ob = g_rpn1h + (size_t)n * 384 * HW;
    #pragma unroll
    for (int mf = 0; mf < 4; mf++) {
        int r0 = m0 + wm + mf * 16 + g;
        float bv0 = b_c1[r0], bv1 = b_c1[r0 + 8];
        #pragma unroll
        for (int nf = 0; nf < 8; nf++) {
            int c = n0 + wn + nf * 8 + t4 * 2;
            float x0 = fmaxf(acc[mf][nf][0] + bv0, 0.f);
            float x1 = fmaxf(acc[mf][nf][1] + bv0, 0.f);
            float x2 = fmaxf(acc[mf][nf][2] + bv1, 0.f);
            float x3 = fmaxf(acc[mf][nf][3] + bv1, 0.f);
            *(__half2*)(ob + (size_t)r0 * HW + c)       = __floats2half2_rn(x0, x1);
            *(__half2*)(ob + (size_t)(r0 + 8) * HW + c) = __floats2half2_rn(x2, x3);
        }
    }
}

// ---------------------------------------------------------------------------
// Kernel 3: head. fp16 MMA + full ldmatrix. 4 warps of 32x64, 128 thr.
// 24 K16 stages, 4-stage ring. Bias + paired softmax (c, c+9) for cls,
// bias for box, two zero scalars. Cs overlay needs 33792B.
// ---------------------------------------------------------------------------
#define HD_A_B  3072
#define HD_B_B  4352
#define HD_ST_B (HD_A_B + HD_B_B)   // 7424
#define HD_SMEM 34048               // max(4*7424=29696, Cs 33792) + pad

__global__ __launch_bounds__(128)
void k_head(const float* __restrict__ b_cls, const float* __restrict__ b_box,
            float* __restrict__ out)
{
    extern __shared__ char ds[];
    const int n  = blockIdx.z;
    const int n0 = blockIdx.x * 128;
    const __half* Bp = g_rpn1h + (size_t)n * 384 * HW + n0;

    const int tid  = threadIdx.x;
    const int warp = tid >> 5, lane = tid & 31;
    const int wm = (warp >> 1) * 32, wn = (warp & 1) * 64;
    const int g  = lane >> 2, t4 = lane & 3;
    const int l15 = lane & 15, l16 = lane >> 4;

    auto loadT = [&](int s) {
        if (s < 24) {
            char* As = ds + (s & 3) * HD_ST_B;
            char* Bs = As + HD_A_B;
            const int k0 = s * 16;
            {
                int row = tid >> 1, sub = tid & 1;  // 128 chunks
                cp16(sptr(As + row * 48 + sub * 16),
                     g_whh + (size_t)row * 384 + k0 + sub * 8, true);
            }
            #pragma unroll
            for (int j = 0; j < 2; j++) {
                int e = tid + j * 128;
                int row = e >> 4, xu = e & 15;
                cp16(sptr(Bs + row * 272 + xu * 16),
                     Bp + (size_t)(k0 + row) * HW + xu * 8, true);
            }
        }
        cpcommit();
    };

    auto ldmAB = [&](int s, unsigned (&a)[2][4], unsigned (&b)[8][2]) {
        const char* As = ds + (s & 3) * HD_ST_B;
        const char* Bs = As + HD_A_B;
        #pragma unroll
        for (int mf = 0; mf < 2; mf++) {
            unsigned addr = sptr(As) + (wm + mf * 16 + l15) * 48 + l16 * 16;
            ldm4(addr, a[mf][0], a[mf][1], a[mf][2], a[mf][3]);
        }
        #pragma unroll
        for (int p = 0; p < 4; p++) {
            unsigned addr = sptr(Bs) + l15 * 272 + (wn + p * 16 + l16 * 8) * 2;
            ldm4t(addr, b[2*p][0], b[2*p][1], b[2*p+1][0], b[2*p+1][1]);
        }
    };

    float acc[2][8][4] = {};
    unsigned aA[2][4], bA[8][2], aB[2][4], bB[8][2];

    loadT(0); loadT(1); loadT(2);
    cpwait1();
    __syncthreads();
    ldmAB(0, aA, bA);

    for (int u = 0; u < 12; u++) {
        const int t0 = 2 * u;
        if (t0) { cpwait1(); __syncthreads(); }
        loadT(t0 + 3);
        ldmAB(t0 + 1, aB, bB);
        #pragma unroll
        for (int mf = 0; mf < 2; mf++)
            #pragma unroll
            for (int nf = 0; nf < 8; nf++) mma16(acc[mf][nf], aA[mf], bA[nf]);

        cpwait1(); __syncthreads();
        loadT(t0 + 4);
        if (t0 + 2 < 24) ldmAB(t0 + 2, aA, bA);
        #pragma unroll
        for (int mf = 0; mf < 2; mf++)
            #pragma unroll
            for (int nf = 0; nf < 8; nf++) mma16(acc[mf][nf], aB[mf], bB[nf]);
    }

    __syncthreads();                       // all warps done reading ring
    float (*Cs)[132] = (float(*)[132])ds;  // overlay
    #pragma unroll
    for (int mf = 0; mf < 2; mf++) {
        int r0 = wm + mf * 16 + g;
        #pragma unroll
        for (int nf = 0; nf < 8; nf++) {
            int c = wn + nf * 8 + t4 * 2;
            Cs[r0][c]         = acc[mf][nf][0];
            Cs[r0][c + 1]     = acc[mf][nf][1];
            Cs[r0 + 8][c]     = acc[mf][nf][2];
            Cs[r0 + 8][c + 1] = acc[mf][nf][3];
        }
    }
    __syncthreads();

    const size_t F1 = (size_t)CB * CIN * HW;
    const size_t F2 = F1 + (size_t)CB * 18 * HW;
    const size_t F3 = F2 + (size_t)CB * 36 * HW;

    for (int it = tid; it < 9 * 128; it += 128) {
        int c = it >> 7, j = it & 127;
        float s0 = Cs[c][j]     + b_cls[c];
        float s1 = Cs[c + 9][j] + b_cls[c + 9];
        float m  = fmaxf(s0, s1);
        float e0 = expf(s0 - m), e1 = expf(s1 - m);
        float inv = 1.f / (e0 + e1);
        out[F1 + (size_t)n * 18 * HW + (size_t)c * HW + n0 + j]       = e0 * inv;
        out[F1 + (size_t)n * 18 * HW + (size_t)(c + 9) * HW + n0 + j] = e1 * inv;
    }
    for (int it = tid; it < 36 * 128; it += 128) {
        int c = it >> 7, j = it & 127;
        out[F2 + (size_t)n * 36 * HW + (size_t)c * HW + n0 + j] = Cs[18 + c][j] + b_box[c];
    }
    if (n == 0 && blockIdx.x == 0 && tid == 0) {
        out[F3]     = 0.f;
        out[F3 + 1] = 0.f;
    }
}

// ---------------------------------------------------------------------------
extern "C" void kernel_launch(void* const* d_in, const int* in_sizes, int n_in,
                              void* d_out, int out_size)
{
    const float* base  = (const float*)d_in[0];
    const float* w_f   = (const float*)d_in[3];
    const float* b_f   = (const float*)d_in[4];
    const float* w_2   = (const float*)d_in[5];
    const float* b_2   = (const float*)d_in[6];
    const float* w_c1  = (const float*)d_in[7];
    const float* b_c1  = (const float*)d_in[8];
    const float* w_cls = (const float*)d_in[9];
    const float* b_cls = (const float*)d_in[10];
    const float* w_box = (const float*)d_in[11];
    const float* b_box = (const float*)d_in[12];
    float* out = (float*)d_out;

    static bool attr_set = false;
    if (!attr_set) {
        cudaFuncSetAttribute(k_conv1, cudaFuncAttributeMaxDynamicSharedMemorySize, C1_SMEM);
        cudaFuncSetAttribute(k_conv3, cudaFuncAttributeMaxDynamicSharedMemorySize, C3_SMEM);
        cudaFuncSetAttribute(k_head,  cudaFuncAttributeMaxDynamicSharedMemorySize, HD_SMEM);
        attr_set = true;
    }

    k_prep <<<(PREP_TOT + 255) / 256, 256>>>(base, w_f, w_2, w_c1, w_cls, w_box);
    k_conv1<<<dim3(32, 4, CB), 128, C1_SMEM>>>(b_f, b_2, out);
    k_conv3<<<dim3(32, 3, CB), 128, C3_SMEM>>>(b_c1);
    k_head <<<dim3(32, 1, CB), 128, HD_SMEM>>>(b_cls, b_box, out);
}